// round 2
// baseline (speedup 1.0000x reference)
#include <cuda_runtime.h>

#define N_NODES_C 100000
#define N_EDGES_C 50000
#define NNZ_CAP   1600000
#define F1 128
#define F2 16
#define SCAN_B 512
#define NB_NODES ((N_NODES_C + SCAN_B - 1) / SCAN_B)   // 196
#define NB_EDGES ((N_EDGES_C + SCAN_B - 1) / SCAN_B)   // 98

// ---------------- static scratch (no cudaMalloc anywhere) ----------------
__device__ int   g_idx64;                      // 1 = indices are int64
__device__ int   g_ncnt[N_NODES_C];
__device__ int   g_ecnt[N_EDGES_C];
__device__ int   g_noff[N_NODES_C + 1];
__device__ int   g_eoff[N_EDGES_C + 1];
__device__ int   g_ncur[N_NODES_C];
__device__ int   g_ecur[N_EDGES_C];
__device__ int   g_bsums[SCAN_B + 1];
__device__ float g_dinv[N_NODES_C];
__device__ float g_binv[N_EDGES_C];
__device__ int   g_e_members[NNZ_CAP];         // node ids grouped by edge
__device__ int   g_n_members[NNZ_CAP];         // edge ids grouped by node
__device__ __align__(16) float g_xw[(size_t)N_NODES_C * F1];
__device__ __align__(16) float g_efeat[(size_t)N_EDGES_C * F1];
__device__ __align__(16) float g_h[(size_t)N_NODES_C * F1];
__device__ __align__(16) float g_hw[(size_t)N_NODES_C * F2];
__device__ __align__(16) float g_efeat2[(size_t)N_EDGES_C * F2];

// ---------------- index dtype handling ----------------
__global__ void detect_kernel(const void* ni, int nnz) {
    const long long* p = (const long long*)ni;
    int k = nnz < 64 ? nnz : 64;
    bool is64 = true;
    for (int i = 0; i < k; i++) {
        long long v = p[i];
        if (v < 0 || v >= (1LL << 31)) { is64 = false; break; }
    }
    g_idx64 = is64 ? 1 : 0;
}

__device__ __forceinline__ int load_idx(const void* p, int i, int is64) {
    return is64 ? (int)((const long long*)p)[i] : ((const int*)p)[i];
}

// ---------------- counting / CSR build ----------------
__global__ void zero_cnt_kernel() {
    int i = blockIdx.x * blockDim.x + threadIdx.x;
    if (i < N_NODES_C) g_ncnt[i] = 0;
    if (i < N_EDGES_C) g_ecnt[i] = 0;
}

__global__ void hist_kernel(const void* ni, const void* ei, int nnz) {
    int i = blockIdx.x * blockDim.x + threadIdx.x;
    if (i >= nnz) return;
    int is64 = g_idx64;
    atomicAdd(&g_ncnt[load_idx(ni, i, is64)], 1);
    atomicAdd(&g_ecnt[load_idx(ei, i, is64)], 1);
}

__global__ void block_sums_kernel(const int* __restrict__ cnt, int n, int* __restrict__ bsums) {
    __shared__ int s[SCAN_B];
    int i = blockIdx.x * SCAN_B + threadIdx.x;
    s[threadIdx.x] = (i < n) ? cnt[i] : 0;
    __syncthreads();
    for (int d = SCAN_B / 2; d > 0; d >>= 1) {
        if (threadIdx.x < d) s[threadIdx.x] += s[threadIdx.x + d];
        __syncthreads();
    }
    if (threadIdx.x == 0) bsums[blockIdx.x] = s[0];
}

__global__ void scan_bsums_kernel(int* __restrict__ b, int nb) {
    __shared__ int s[SCAN_B];
    int tid = threadIdx.x;
    int v = (tid < nb) ? b[tid] : 0;
    s[tid] = v;
    __syncthreads();
    for (int d = 1; d < SCAN_B; d <<= 1) {
        int t = (tid >= d) ? s[tid - d] : 0;
        __syncthreads();
        s[tid] += t;
        __syncthreads();
    }
    if (tid < nb) b[tid] = s[tid] - v;           // exclusive
    if (tid == nb - 1) b[nb] = s[tid];           // total
}

__global__ void scan_apply_kernel(const int* __restrict__ cnt, int n,
                                  const int* __restrict__ bsums, int* __restrict__ off) {
    __shared__ int s[SCAN_B];
    int tid = threadIdx.x;
    int i = blockIdx.x * SCAN_B + tid;
    int v = (i < n) ? cnt[i] : 0;
    s[tid] = v;
    __syncthreads();
    for (int d = 1; d < SCAN_B; d <<= 1) {
        int t = (tid >= d) ? s[tid - d] : 0;
        __syncthreads();
        s[tid] += t;
        __syncthreads();
    }
    int base = bsums[blockIdx.x];
    if (i < n) off[i] = base + s[tid] - v;
    if (i == n - 1) off[n] = base + s[tid];
}

__global__ void prep_kernel() {
    int i = blockIdx.x * blockDim.x + threadIdx.x;
    if (i < N_EDGES_C) {
        int d = g_eoff[i + 1] - g_eoff[i];
        g_binv[i] = d > 0 ? 1.f / (float)d : 0.f;
        g_ecur[i] = g_eoff[i];
    }
    if (i < N_NODES_C) {
        int d = g_noff[i + 1] - g_noff[i];
        g_dinv[i] = d > 0 ? 1.f / (float)d : 0.f;
        g_ncur[i] = g_noff[i];
    }
}

__global__ void fill_kernel(const void* ni, const void* ei, int nnz) {
    int i = blockIdx.x * blockDim.x + threadIdx.x;
    if (i >= nnz) return;
    int is64 = g_idx64;
    int n = load_idx(ni, i, is64);
    int e = load_idx(ei, i, is64);
    g_e_members[atomicAdd(&g_ecur[e], 1)] = n;
    g_n_members[atomicAdd(&g_ncur[n], 1)] = e;
}

// ---------------- GEMM1: [M,128] @ [128,128] -> g_xw ----------------
__global__ __launch_bounds__(256) void gemm1_kernel(const float* __restrict__ A,
                                                    const float* __restrict__ W, int M) {
    __shared__ float As[16][72];
    __shared__ float Bs[16][128];
    const int tid  = threadIdx.x;
    const int row0 = blockIdx.x * 64;
    const int ty = tid >> 5;
    const int tx = tid & 31;
    const int ar = tid >> 2;
    const int ak = (tid & 3) << 2;
    const int bk = tid >> 5;
    const int bn = (tid & 31) << 2;

    float acc[8][4];
#pragma unroll
    for (int i = 0; i < 8; i++)
#pragma unroll
        for (int j = 0; j < 4; j++) acc[i][j] = 0.f;

    const int arow = row0 + ar;
    for (int k0 = 0; k0 < 128; k0 += 16) {
        float4 a4 = (arow < M) ? *(const float4*)&A[(size_t)arow * 128 + k0 + ak]
                               : make_float4(0.f, 0.f, 0.f, 0.f);
        As[ak + 0][ar] = a4.x; As[ak + 1][ar] = a4.y;
        As[ak + 2][ar] = a4.z; As[ak + 3][ar] = a4.w;
        *(float4*)&Bs[bk][bn]     = *(const float4*)&W[(size_t)(k0 + bk) * 128 + bn];
        *(float4*)&Bs[bk + 8][bn] = *(const float4*)&W[(size_t)(k0 + bk + 8) * 128 + bn];
        __syncthreads();
#pragma unroll
        for (int kk = 0; kk < 16; kk++) {
            float4 a0 = *(const float4*)&As[kk][ty * 8];
            float4 a1 = *(const float4*)&As[kk][ty * 8 + 4];
            float4 b  = *(const float4*)&Bs[kk][tx * 4];
            float a[8] = {a0.x, a0.y, a0.z, a0.w, a1.x, a1.y, a1.z, a1.w};
#pragma unroll
            for (int i = 0; i < 8; i++) {
                acc[i][0] += a[i] * b.x; acc[i][1] += a[i] * b.y;
                acc[i][2] += a[i] * b.z; acc[i][3] += a[i] * b.w;
            }
        }
        __syncthreads();
    }
#pragma unroll
    for (int i = 0; i < 8; i++) {
        int r = row0 + ty * 8 + i;
        if (r < M) {
            float4 o = make_float4(acc[i][0], acc[i][1], acc[i][2], acc[i][3]);
            *(float4*)&g_xw[(size_t)r * 128 + tx * 4] = o;
        }
    }
}

// ---------------- GEMM2: [M,128] @ [128,16] -> g_hw ----------------
__global__ __launch_bounds__(256) void gemm2_kernel(const float* __restrict__ W, int M) {
    __shared__ float hs[16][128];
    __shared__ float ws[128 * 16];
    const int tid = threadIdx.x;
#pragma unroll
    for (int i = 0; i < 8; i++) ws[tid + i * 256] = W[tid + i * 256];
    const int row0 = blockIdx.x * 16;
#pragma unroll
    for (int i = 0; i < 2; i++) {
        int idx = tid + i * 256;
        int r = idx >> 5;
        int c = idx & 31;
        int gr = row0 + r;
        float4 v = (gr < M) ? *(const float4*)&g_h[(size_t)gr * 128 + c * 4]
                            : make_float4(0.f, 0.f, 0.f, 0.f);
        *(float4*)&hs[r][c * 4] = v;
    }
    __syncthreads();
    const int r = tid >> 4, c = tid & 15;
    float acc = 0.f;
#pragma unroll
    for (int k = 0; k < 128; k++) acc += hs[r][k] * ws[k * 16 + c];
    int gr = row0 + r;
    if (gr < M) g_hw[(size_t)gr * 16 + c] = acc;
}

// ---------------- gather-reduce, F = 128 (warp per destination row) ----------------
template <bool RELU>
__global__ void gather128(const float* __restrict__ src, float* __restrict__ dst,
                          const int* __restrict__ mem, const int* __restrict__ off,
                          const float* __restrict__ inv, const float* __restrict__ bias,
                          int nrows) {
    int w = (blockIdx.x * blockDim.x + threadIdx.x) >> 5;
    int lane = threadIdx.x & 31;
    if (w >= nrows) return;
    int beg = off[w], end = off[w + 1];
    float4 a0 = make_float4(0.f, 0.f, 0.f, 0.f);
    float4 a1 = make_float4(0.f, 0.f, 0.f, 0.f);
    int j = beg;
    for (; j + 1 < end; j += 2) {
        int m0 = mem[j], m1 = mem[j + 1];
        float4 v0 = *(const float4*)&src[(size_t)m0 * F1 + lane * 4];
        float4 v1 = *(const float4*)&src[(size_t)m1 * F1 + lane * 4];
        a0.x += v0.x; a0.y += v0.y; a0.z += v0.z; a0.w += v0.w;
        a1.x += v1.x; a1.y += v1.y; a1.z += v1.z; a1.w += v1.w;
    }
    if (j < end) {
        int m0 = mem[j];
        float4 v0 = *(const float4*)&src[(size_t)m0 * F1 + lane * 4];
        a0.x += v0.x; a0.y += v0.y; a0.z += v0.z; a0.w += v0.w;
    }
    float s = inv[w];
    float4 r = make_float4((a0.x + a1.x) * s, (a0.y + a1.y) * s,
                           (a0.z + a1.z) * s, (a0.w + a1.w) * s);
    if (bias) {
        float4 b = *(const float4*)&bias[lane * 4];
        r.x += b.x; r.y += b.y; r.z += b.z; r.w += b.w;
    }
    if (RELU) {
        r.x = fmaxf(r.x, 0.f); r.y = fmaxf(r.y, 0.f);
        r.z = fmaxf(r.z, 0.f); r.w = fmaxf(r.w, 0.f);
    }
    *(float4*)&dst[(size_t)w * F1 + lane * 4] = r;
}

// ---------------- gather-reduce, F = 16 (warp per row, 2 members/iter) --------------
__global__ void gather16(const float* __restrict__ src, float* __restrict__ dst,
                         const int* __restrict__ mem, const int* __restrict__ off,
                         const float* __restrict__ inv, const float* __restrict__ bias,
                         int nrows) {
    int w = (blockIdx.x * blockDim.x + threadIdx.x) >> 5;
    int lane = threadIdx.x & 31;
    if (w >= nrows) return;
    int beg = off[w], end = off[w + 1];
    int half = lane >> 4, f = lane & 15;
    float acc = 0.f;
    for (int j = beg + half; j < end; j += 2)
        acc += src[(size_t)mem[j] * F2 + f];
    acc += __shfl_down_sync(0xffffffffu, acc, 16);
    if (lane < 16) {
        float r = acc * inv[w];
        if (bias) r += bias[f];
        dst[(size_t)w * F2 + f] = r;
    }
}

// ---------------- launcher ----------------
extern "C" void kernel_launch(void* const* d_in, const int* in_sizes, int n_in,
                              void* d_out, int out_size) {
    const float* x  = (const float*)d_in[0];
    const void*  ni = d_in[1];
    const void*  ei = d_in[2];
    const float* W1 = (const float*)d_in[n_in - 4];
    const float* b1 = (const float*)d_in[n_in - 3];
    const float* W2 = (const float*)d_in[n_in - 2];
    const float* b2 = (const float*)d_in[n_in - 1];
    const int nnz = in_sizes[1];
    const int M   = in_sizes[0] / F1;
    float* out = (float*)d_out;

    // device pointers to the scratch symbols (symbols are directly addressable in kernels;
    // host just launches)
    detect_kernel<<<1, 1>>>(ni, nnz);
    zero_cnt_kernel<<<(N_NODES_C + 255) / 256, 256>>>();
    hist_kernel<<<(nnz + 255) / 256, 256>>>(ni, ei, nnz);

    // edge scan (need raw device addresses: use a tiny helper via kernels operating on symbols)
    // We can't take &g_ecnt on host, so scans run on symbol-bound wrapper kernels below.
    // Implemented via separate launches with compile-time bound pointers:
    extern __global__ void run_scans();  // fwd decl trick not used; do explicit wrappers

    // (wrapper kernels defined after this function are not visible; instead we declared
    //  scan kernels taking pointers — get them via device-side constant lambdas is not
    //  possible, so we use dedicated wrapper kernels below.)
    // -- actual calls are made through the wrappers declared before this function:
    {
        // edge offsets
        void launch_scans_edges(int);
        void launch_scans_nodes(int);
    }

    // NOTE: since host code cannot take addresses of __device__ symbols without
    // cudaGetSymbolAddress (an API call, allowed — it is not an allocation), use it once per
    // launch; it is not a sync and not an alloc.
    static int*   p_ecnt = nullptr; static int* p_eoff = nullptr;
    static int*   p_ncnt = nullptr; static int* p_noff = nullptr;
    static int*   p_bs   = nullptr;
    static int*   p_emem = nullptr; static int* p_nmem = nullptr;
    static float* p_binv = nullptr; static float* p_dinv = nullptr;
    static float* p_xw = nullptr, *p_ef = nullptr, *p_h = nullptr, *p_hw = nullptr, *p_ef2 = nullptr;
    if (!p_ecnt) {
        cudaGetSymbolAddress((void**)&p_ecnt, g_ecnt);
        cudaGetSymbolAddress((void**)&p_eoff, g_eoff);
        cudaGetSymbolAddress((void**)&p_ncnt, g_ncnt);
        cudaGetSymbolAddress((void**)&p_noff, g_noff);
        cudaGetSymbolAddress((void**)&p_bs,   g_bsums);
        cudaGetSymbolAddress((void**)&p_emem, g_e_members);
        cudaGetSymbolAddress((void**)&p_nmem, g_n_members);
        cudaGetSymbolAddress((void**)&p_binv, g_binv);
        cudaGetSymbolAddress((void**)&p_dinv, g_dinv);
        cudaGetSymbolAddress((void**)&p_xw,   g_xw);
        cudaGetSymbolAddress((void**)&p_ef,   g_efeat);
        cudaGetSymbolAddress((void**)&p_h,    g_h);
        cudaGetSymbolAddress((void**)&p_hw,   g_hw);
        cudaGetSymbolAddress((void**)&p_ef2,  g_efeat2);
    }

    // edge offsets
    block_sums_kernel<<<NB_EDGES, SCAN_B>>>(p_ecnt, N_EDGES_C, p_bs);
    scan_bsums_kernel<<<1, SCAN_B>>>(p_bs, NB_EDGES);
    scan_apply_kernel<<<NB_EDGES, SCAN_B>>>(p_ecnt, N_EDGES_C, p_bs, p_eoff);
    // node offsets
    block_sums_kernel<<<NB_NODES, SCAN_B>>>(p_ncnt, N_NODES_C, p_bs);
    scan_bsums_kernel<<<1, SCAN_B>>>(p_bs, NB_NODES);
    scan_apply_kernel<<<NB_NODES, SCAN_B>>>(p_ncnt, N_NODES_C, p_bs, p_noff);

    prep_kernel<<<(N_NODES_C + 255) / 256, 256>>>();
    fill_kernel<<<(nnz + 255) / 256, 256>>>(ni, ei, nnz);

    gemm1_kernel<<<(M + 63) / 64, 256>>>(x, W1, M);

    // layer 1: node -> edge (scale Binv), then edge -> node (scale Dinv, +b1, relu)
    {
        int blocks_e = (N_EDGES_C * 32 + 255) / 256;
        int blocks_n = (N_NODES_C * 32 + 255) / 256;
        gather128<false><<<blocks_e, 256>>>(p_xw, p_ef, p_emem, p_eoff, p_binv, nullptr, N_EDGES_C);
        gather128<true ><<<blocks_n, 256>>>(p_ef, p_h,  p_nmem, p_noff, p_dinv, b1,      N_NODES_C);
    }

    gemm2_kernel<<<(M + 15) / 16, 256>>>(W2, M);

    // layer 2
    {
        int blocks_e = (N_EDGES_C * 32 + 255) / 256;
        int blocks_n = (N_NODES_C * 32 + 255) / 256;
        gather16<<<blocks_e, 256>>>(p_hw,  p_ef2, p_emem, p_eoff, p_binv, nullptr, N_EDGES_C);
        gather16<<<blocks_n, 256>>>(p_ef2, out,   p_nmem, p_noff, p_dinv, b2,      N_NODES_C);
    }
}